// round 2
// baseline (speedup 1.0000x reference)
#include <cuda_runtime.h>
#include <cstdint>
#include <cstddef>

// Problem shapes (fixed per reference)
#define B_ 4
#define N_ 2048
#define DIM_ 1024
#define H_ 16
#define DH_ 64
#define QKV_COLS (3 * H_ * DH_)   // 3072
#define HD_ (H_ * DH_)            // 1024

// Scratch: __device__ globals (allocation-free rule)
__device__ float g_qkv[(size_t)B_ * N_ * QKV_COLS];   // [B,N,3072]
__device__ float g_attn[(size_t)B_ * N_ * HD_];       // [B,N,1024]

// ---------------------------------------------------------------------------
// SGEMM: C[M,Nc] = A[M,K] @ B[K,Nc] (+ bias). 128x128 tile, 8x8/thread, BK=8.
// Requires M%128==0, Nc%128==0, K%8==0 (true for all three calls).
// ---------------------------------------------------------------------------
template<bool HAS_BIAS>
__global__ __launch_bounds__(256, 2) void sgemm_kernel(
    const float* __restrict__ A, const float* __restrict__ Bm,
    const float* __restrict__ bias, float* __restrict__ C,
    int M, int Nc, int K)
{
    __shared__ float As[8][128];
    __shared__ float Bs[8][128];

    const int tid = threadIdx.x;
    const int tx = tid & 15;        // 0..15 -> col group
    const int ty = tid >> 4;        // 0..15 -> row group
    const int m0 = blockIdx.y * 128;
    const int n0 = blockIdx.x * 128;

    float acc[8][8];
#pragma unroll
    for (int i = 0; i < 8; i++)
#pragma unroll
        for (int j = 0; j < 8; j++) acc[i][j] = 0.f;

    const int arow = tid >> 1;            // 0..127
    const int acol4 = (tid & 1) * 4;      // 0 or 4
    const int brow = tid >> 5;            // 0..7
    const int bcol4 = (tid & 31) * 4;     // 0..124

    const float* Aptr = A + (size_t)(m0 + arow) * K + acol4;
    const float* Bptr = Bm + (size_t)brow * Nc + n0 + bcol4;

    for (int kt = 0; kt < K; kt += 8) {
        float4 av = *(const float4*)(Aptr + kt);
        As[acol4 + 0][arow] = av.x;
        As[acol4 + 1][arow] = av.y;
        As[acol4 + 2][arow] = av.z;
        As[acol4 + 3][arow] = av.w;
        *(float4*)&Bs[brow][bcol4] = *(const float4*)(Bptr + (size_t)kt * Nc);
        __syncthreads();

#pragma unroll
        for (int k = 0; k < 8; k++) {
            float ra[8], rb[8];
            *(float4*)&ra[0] = *(float4*)&As[k][ty * 8];
            *(float4*)&ra[4] = *(float4*)&As[k][ty * 8 + 4];
            *(float4*)&rb[0] = *(float4*)&Bs[k][tx * 8];
            *(float4*)&rb[4] = *(float4*)&Bs[k][tx * 8 + 4];
#pragma unroll
            for (int i = 0; i < 8; i++)
#pragma unroll
                for (int j = 0; j < 8; j++)
                    acc[i][j] += ra[i] * rb[j];
        }
        __syncthreads();
    }

#pragma unroll
    for (int i = 0; i < 8; i++) {
        const int row = m0 + ty * 8 + i;
        float* crow = C + (size_t)row * Nc + n0 + tx * 8;
        float4 o0 = make_float4(acc[i][0], acc[i][1], acc[i][2], acc[i][3]);
        float4 o1 = make_float4(acc[i][4], acc[i][5], acc[i][6], acc[i][7]);
        if (HAS_BIAS) {
            const float* bb = bias + n0 + tx * 8;
            o0.x += bb[0]; o0.y += bb[1]; o0.z += bb[2]; o0.w += bb[3];
            o1.x += bb[4]; o1.y += bb[5]; o1.z += bb[6]; o1.w += bb[7];
        }
        *(float4*)(crow)     = o0;
        *(float4*)(crow + 4) = o1;
    }
}

// ---------------------------------------------------------------------------
// Flash attention (causal + key-padding mask). One block = (b, h, 64 q-rows).
// 256 threads as 16x16 grid, each owns 4x4 micro-tiles of S and O.
// Online softmax across key tiles of 64.
// ---------------------------------------------------------------------------
struct AttnSmem {
    float Qt[64][64];   // [d][r]  (transposed Q tile, pre-scaled)
    float Kt[64][64];   // [d][j]  (transposed K tile)
    float Vs[64][68];   // [j][d]  (padded for banks, float4-aligned rows)
    float Ps[64][68];   // [r][j]
    float mk[64];       // additive key-padding mask for this tile
};

__global__ __launch_bounds__(256, 3) void flash_attn_kernel(
    const float* __restrict__ qkv, const int* __restrict__ mask,
    float* __restrict__ outp)
{
    extern __shared__ char smem_raw[];
    AttnSmem& sm = *reinterpret_cast<AttnSmem*>(smem_raw);

    const int qt = blockIdx.x;          // query tile (64 rows)
    const int h  = blockIdx.y;
    const int b  = blockIdx.z;
    const int tid = threadIdx.x;
    const int tx = tid & 15;            // col group (4 cols each)
    const int ty = tid >> 4;            // row group (4 rows each)

    const float scale = 0.125f;         // DH^-0.5 = 64^-0.5

    const float* qbase = qkv + (size_t)b * N_ * QKV_COLS + h * DH_;
    const float* kbase = qbase + HD_;
    const float* vbase = qbase + 2 * HD_;

    // Load Q tile -> Qt[d][r], pre-scaled
    {
        const int r = tid >> 2;             // 0..63
        const int d0 = (tid & 3) * 16;      // 0,16,32,48
        const int ig = qt * 64 + r;
        const float* qr = qbase + (size_t)ig * QKV_COLS + d0;
#pragma unroll
        for (int dd = 0; dd < 16; dd++)
            sm.Qt[d0 + dd][r] = qr[dd] * scale;
    }

    float m_s[4], l_s[4], acc[4][4];
#pragma unroll
    for (int r = 0; r < 4; r++) {
        m_s[r] = -1e30f; l_s[r] = 0.f;
#pragma unroll
        for (int c = 0; c < 4; c++) acc[r][c] = 0.f;
    }
    int ig[4];
#pragma unroll
    for (int r = 0; r < 4; r++) ig[r] = qt * 64 + ty * 4 + r;

    for (int kt = 0; kt <= qt; kt++) {
        // --- load K (transposed), V, mask tile ---
        {
            const int j = tid >> 2;
            const int d0 = (tid & 3) * 16;
            const int jg = kt * 64 + j;
            const float* kr = kbase + (size_t)jg * QKV_COLS + d0;
            const float* vr = vbase + (size_t)jg * QKV_COLS + d0;
#pragma unroll
            for (int dd = 0; dd < 16; dd++) {
                sm.Kt[d0 + dd][j] = kr[dd];
                sm.Vs[j][d0 + dd] = vr[dd];
            }
            if (tid < 64)
                sm.mk[tid] = (mask[(size_t)b * N_ + kt * 64 + tid] != 0) ? 0.f : -1e30f;
        }
        __syncthreads();

        // --- S = Q K^T (4x4 per thread) ---
        float s[4][4];
#pragma unroll
        for (int r = 0; r < 4; r++)
#pragma unroll
            for (int c = 0; c < 4; c++) s[r][c] = 0.f;

#pragma unroll 8
        for (int d = 0; d < 64; d++) {
            float4 qv = *(float4*)&sm.Qt[d][ty * 4];
            float4 kv = *(float4*)&sm.Kt[d][tx * 4];
            float rq[4] = {qv.x, qv.y, qv.z, qv.w};
            float rk[4] = {kv.x, kv.y, kv.z, kv.w};
#pragma unroll
            for (int r = 0; r < 4; r++)
#pragma unroll
                for (int c = 0; c < 4; c++)
                    s[r][c] += rq[r] * rk[c];
        }

        // --- masks ---
#pragma unroll
        for (int c = 0; c < 4; c++) {
            const float mv = sm.mk[tx * 4 + c];
#pragma unroll
            for (int r = 0; r < 4; r++) s[r][c] += mv;
        }
        if (kt == qt) {
#pragma unroll
            for (int r = 0; r < 4; r++) {
#pragma unroll
                for (int c = 0; c < 4; c++) {
                    const int jg = kt * 64 + tx * 4 + c;
                    if (jg > ig[r]) s[r][c] = -1e30f;
                }
            }
        }

        // --- online softmax (row stats across 16 tx-threads via shfl) ---
        float rmax[4], rsum[4];
#pragma unroll
        for (int r = 0; r < 4; r++) {
            float mx = fmaxf(fmaxf(s[r][0], s[r][1]), fmaxf(s[r][2], s[r][3]));
#pragma unroll
            for (int o = 1; o < 16; o <<= 1)
                mx = fmaxf(mx, __shfl_xor_sync(0xffffffffu, mx, o));
            rmax[r] = mx;
        }
#pragma unroll
        for (int r = 0; r < 4; r++) {
            const float mnew = fmaxf(m_s[r], rmax[r]);
            const float corr = __expf(m_s[r] - mnew);
            m_s[r] = mnew;
            float su = 0.f;
#pragma unroll
            for (int c = 0; c < 4; c++) {
                s[r][c] = __expf(s[r][c] - mnew);
                su += s[r][c];
            }
            rsum[r] = su;
            l_s[r] *= corr;
#pragma unroll
            for (int c = 0; c < 4; c++) acc[r][c] *= corr;
        }
#pragma unroll
        for (int r = 0; r < 4; r++) {
            float su = rsum[r];
#pragma unroll
            for (int o = 1; o < 16; o <<= 1)
                su += __shfl_xor_sync(0xffffffffu, su, o);
            l_s[r] += su;
        }

        // --- store P ---
#pragma unroll
        for (int r = 0; r < 4; r++)
#pragma unroll
            for (int c = 0; c < 4; c++)
                sm.Ps[ty * 4 + r][tx * 4 + c] = s[r][c];
        __syncthreads();

        // --- O += P @ V ---
#pragma unroll 4
        for (int j = 0; j < 64; j++) {
            float pr[4];
#pragma unroll
            for (int r = 0; r < 4; r++) pr[r] = sm.Ps[ty * 4 + r][j];
            float4 vv = *(float4*)&sm.Vs[j][tx * 4];
            float rv[4] = {vv.x, vv.y, vv.z, vv.w};
#pragma unroll
            for (int r = 0; r < 4; r++)
#pragma unroll
                for (int c = 0; c < 4; c++)
                    acc[r][c] += pr[r] * rv[c];
        }
        __syncthreads();   // before next iteration overwrites Kt/Vs/Ps
    }

    // --- epilogue ---
#pragma unroll
    for (int r = 0; r < 4; r++) {
        const float inv = 1.f / l_s[r];
        const int i = ig[r];
        float4 o = make_float4(acc[r][0] * inv, acc[r][1] * inv,
                               acc[r][2] * inv, acc[r][3] * inv);
        *(float4*)&outp[((size_t)b * N_ + i) * HD_ + h * DH_ + tx * 4] = o;
    }
}

// ---------------------------------------------------------------------------
extern "C" void kernel_launch(void* const* d_in, const int* in_sizes, int n_in,
                              void* d_out, int out_size)
{
    const float* x     = (const float*)d_in[0];
    const int*   mask  = (const int*)d_in[1];     // bool -> int32 in harness
    const float* w_qkv = (const float*)d_in[2];
    const float* w_out = (const float*)d_in[3];
    const float* b_out = (const float*)d_in[4];
    float* out = (float*)d_out;

    float *qkv_buf = nullptr, *attn_buf = nullptr;
    cudaGetSymbolAddress((void**)&qkv_buf, g_qkv);
    cudaGetSymbolAddress((void**)&attn_buf, g_attn);

    cudaFuncSetAttribute(flash_attn_kernel,
                         cudaFuncAttributeMaxDynamicSharedMemorySize,
                         (int)sizeof(AttnSmem));

    const int M = B_ * N_;   // 8192

    // 1) QKV projection: [8192,1024] @ [1024,3072]
    sgemm_kernel<false><<<dim3(QKV_COLS / 128, M / 128), 256>>>(
        x, w_qkv, nullptr, qkv_buf, M, QKV_COLS, DIM_);

    // 2) causal flash attention
    flash_attn_kernel<<<dim3(N_ / 64, H_, B_), 256, sizeof(AttnSmem)>>>(
        qkv_buf, mask, attn_buf);

    // 3) output projection + bias: [8192,1024] @ [1024,1024] + b_out
    sgemm_kernel<true><<<dim3(DIM_ / 128, M / 128), 256>>>(
        attn_buf, w_out, b_out, out, M, DIM_, DIM_);
}

// round 3
// speedup vs baseline: 1.0089x; 1.0089x over previous
#include <cuda_runtime.h>
#include <cstdint>
#include <cstddef>

// Problem shapes (fixed per reference)
#define B_ 4
#define N_ 2048
#define DIM_ 1024
#define H_ 16
#define DH_ 64
#define QKV_COLS (3 * H_ * DH_)   // 3072
#define HD_ (H_ * DH_)            // 1024

// Scratch: __device__ globals (allocation-free rule)
__device__ float g_qkv[(size_t)B_ * N_ * QKV_COLS];   // [B,N,3072]
__device__ float g_attn[(size_t)B_ * N_ * HD_];       // [B,N,1024]

// ---------------------------------------------------------------------------
// tf32 helpers
// ---------------------------------------------------------------------------
__device__ __forceinline__ uint32_t f2tf32(float x) {
    uint32_t r;
    asm("cvt.rna.tf32.f32 %0, %1;" : "=r"(r) : "f"(x));
    return r;
}

__device__ __forceinline__ void mma_tf32_16x8x8(
    float& d0, float& d1, float& d2, float& d3,
    uint32_t a0, uint32_t a1, uint32_t a2, uint32_t a3,
    uint32_t b0, uint32_t b1)
{
    asm volatile(
        "mma.sync.aligned.m16n8k8.row.col.f32.tf32.tf32.f32 "
        "{%0,%1,%2,%3}, {%4,%5,%6,%7}, {%8,%9}, {%0,%1,%2,%3};\n"
        : "+f"(d0), "+f"(d1), "+f"(d2), "+f"(d3)
        : "r"(a0), "r"(a1), "r"(a2), "r"(a3), "r"(b0), "r"(b1));
}

// ---------------------------------------------------------------------------
// TF32 tensor-core GEMM: C[M,Nc] = A[M,K] @ B[K,Nc] (+bias).
// Block: 256 thr = 8 warps in 2(m)x4(n); warp computes 64x32.
// Tile: BM=128, BN=128, BK=32. Fragment-shuffled smem:
//   As[kstep][m16tile][lane][4]  -> one LDS.128 per A-frag
//   Bs[kstep][n8tile][lane][2]   -> one LDS.64  per B-frag
// m16n8k8 fragment maps (PTX):
//   A: lane=(mm%8)*4+(kk%4), reg=(kk/4)*2+(mm/8)
//   B: lane=(nn)*4+(kk%4),   reg=kk/4
//   C: row=lane/4 (+8), col=(lane%4)*2 (+1)
// ---------------------------------------------------------------------------
template<bool HAS_BIAS>
__global__ __launch_bounds__(256, 2) void gemm_tf32_kernel(
    const float* __restrict__ A, const float* __restrict__ Bm,
    const float* __restrict__ bias, float* __restrict__ C,
    int M, int Nc, int K)
{
    __shared__ uint32_t As[4][8][32][4];    // 16 KB
    __shared__ uint32_t Bs[4][16][32][2];   // 16 KB

    const int tid  = threadIdx.x;
    const int lane = tid & 31;
    const int wid  = tid >> 5;
    const int warp_m = wid >> 2;    // 0..1
    const int warp_n = wid & 3;     // 0..3
    const int m0 = blockIdx.y * 128;
    const int n0 = blockIdx.x * 128;

    float acc[4][4][4];
#pragma unroll
    for (int mt = 0; mt < 4; mt++)
#pragma unroll
        for (int nt = 0; nt < 4; nt++)
#pragma unroll
            for (int r = 0; r < 4; r++) acc[mt][nt][r] = 0.f;

    // global-load coords
    const int arow0 = tid >> 3;          // 0..31
    const int acol4 = (tid & 7) * 4;     // 0..28
    const int bk0   = tid >> 5;          // 0..7
    const int bn4   = (tid & 31) * 4;    // 0..124

    for (int kt = 0; kt < K; kt += 32) {
        // ---- stage A tile (128x32) ----
#pragma unroll
        for (int p = 0; p < 4; p++) {
            const int row = arow0 + p * 32;
            float4 v = *(const float4*)(A + (size_t)(m0 + row) * K + kt + acol4);
            const int mt = row >> 4, mm = row & 15;
            const float vv[4] = {v.x, v.y, v.z, v.w};
#pragma unroll
            for (int j = 0; j < 4; j++) {
                const int k = acol4 + j;
                const int ks = k >> 3, kk = k & 7;
                As[ks][mt][(mm & 7) * 4 + (kk & 3)][((kk >> 2) << 1) | (mm >> 3)]
                    = f2tf32(vv[j]);
            }
        }
        // ---- stage B tile (32x128) ----
#pragma unroll
        for (int p = 0; p < 4; p++) {
            const int k = bk0 + p * 8;
            const int ks = k >> 3, kk = k & 7;
            float4 v = *(const float4*)(Bm + (size_t)(kt + k) * Nc + n0 + bn4);
            const float vv[4] = {v.x, v.y, v.z, v.w};
#pragma unroll
            for (int j = 0; j < 4; j++) {
                const int n = bn4 + j;
                Bs[ks][n >> 3][(n & 7) * 4 + (kk & 3)][kk >> 2] = f2tf32(vv[j]);
            }
        }
        __syncthreads();

        // ---- compute: 4 k-steps x (4 m-tiles x 4 n-tiles) mma ----
#pragma unroll
        for (int ks = 0; ks < 4; ks++) {
            uint32_t af[4][4];
            uint32_t bf[4][2];
#pragma unroll
            for (int mt = 0; mt < 4; mt++) {
                uint4 t = *(const uint4*)&As[ks][warp_m * 4 + mt][lane][0];
                af[mt][0] = t.x; af[mt][1] = t.y; af[mt][2] = t.z; af[mt][3] = t.w;
            }
#pragma unroll
            for (int nt = 0; nt < 4; nt++) {
                uint2 t = *(const uint2*)&Bs[ks][warp_n * 4 + nt][lane][0];
                bf[nt][0] = t.x; bf[nt][1] = t.y;
            }
#pragma unroll
            for (int mt = 0; mt < 4; mt++)
#pragma unroll
                for (int nt = 0; nt < 4; nt++)
                    mma_tf32_16x8x8(acc[mt][nt][0], acc[mt][nt][1],
                                    acc[mt][nt][2], acc[mt][nt][3],
                                    af[mt][0], af[mt][1], af[mt][2], af[mt][3],
                                    bf[nt][0], bf[nt][1]);
        }
        __syncthreads();
    }

    // ---- epilogue ----
#pragma unroll
    for (int mt = 0; mt < 4; mt++) {
#pragma unroll
        for (int nt = 0; nt < 4; nt++) {
            const int r0 = m0 + warp_m * 64 + mt * 16 + (lane >> 2);
            const int c0 = n0 + warp_n * 32 + nt * 8 + (lane & 3) * 2;
            float2 lo = make_float2(acc[mt][nt][0], acc[mt][nt][1]);
            float2 hi = make_float2(acc[mt][nt][2], acc[mt][nt][3]);
            if (HAS_BIAS) {
                const float b0v = bias[c0], b1v = bias[c0 + 1];
                lo.x += b0v; lo.y += b1v;
                hi.x += b0v; hi.y += b1v;
            }
            *(float2*)(C + (size_t)r0 * Nc + c0)       = lo;
            *(float2*)(C + (size_t)(r0 + 8) * Nc + c0) = hi;
        }
    }
}

// ---------------------------------------------------------------------------
// Flash attention (causal + key-padding mask), fp32 (unchanged from R2).
// ---------------------------------------------------------------------------
struct AttnSmem {
    float Qt[64][64];
    float Kt[64][64];
    float Vs[64][68];
    float Ps[64][68];
    float mk[64];
};

__global__ __launch_bounds__(256, 3) void flash_attn_kernel(
    const float* __restrict__ qkv, const int* __restrict__ mask,
    float* __restrict__ outp)
{
    extern __shared__ char smem_raw[];
    AttnSmem& sm = *reinterpret_cast<AttnSmem*>(smem_raw);

    const int qt = blockIdx.x;
    const int h  = blockIdx.y;
    const int b  = blockIdx.z;
    const int tid = threadIdx.x;
    const int tx = tid & 15;
    const int ty = tid >> 4;

    const float scale = 0.125f;

    const float* qbase = qkv + (size_t)b * N_ * QKV_COLS + h * DH_;
    const float* kbase = qbase + HD_;
    const float* vbase = qbase + 2 * HD_;

    {
        const int r = tid >> 2;
        const int d0 = (tid & 3) * 16;
        const int ig = qt * 64 + r;
        const float* qr = qbase + (size_t)ig * QKV_COLS + d0;
#pragma unroll
        for (int dd = 0; dd < 16; dd++)
            sm.Qt[d0 + dd][r] = qr[dd] * scale;
    }

    float m_s[4], l_s[4], acc[4][4];
#pragma unroll
    for (int r = 0; r < 4; r++) {
        m_s[r] = -1e30f; l_s[r] = 0.f;
#pragma unroll
        for (int c = 0; c < 4; c++) acc[r][c] = 0.f;
    }
    int ig[4];
#pragma unroll
    for (int r = 0; r < 4; r++) ig[r] = qt * 64 + ty * 4 + r;

    for (int kt = 0; kt <= qt; kt++) {
        {
            const int j = tid >> 2;
            const int d0 = (tid & 3) * 16;
            const int jg = kt * 64 + j;
            const float* kr = kbase + (size_t)jg * QKV_COLS + d0;
            const float* vr = vbase + (size_t)jg * QKV_COLS + d0;
#pragma unroll
            for (int dd = 0; dd < 16; dd++) {
                sm.Kt[d0 + dd][j] = kr[dd];
                sm.Vs[j][d0 + dd] = vr[dd];
            }
            if (tid < 64)
                sm.mk[tid] = (mask[(size_t)b * N_ + kt * 64 + tid] != 0) ? 0.f : -1e30f;
        }
        __syncthreads();

        float s[4][4];
#pragma unroll
        for (int r = 0; r < 4; r++)
#pragma unroll
            for (int c = 0; c < 4; c++) s[r][c] = 0.f;

#pragma unroll 8
        for (int d = 0; d < 64; d++) {
            float4 qv = *(float4*)&sm.Qt[d][ty * 4];
            float4 kv = *(float4*)&sm.Kt[d][tx * 4];
            float rq[4] = {qv.x, qv.y, qv.z, qv.w};
            float rk[4] = {kv.x, kv.y, kv.z, kv.w};
#pragma unroll
            for (int r = 0; r < 4; r++)
#pragma unroll
                for (int c = 0; c < 4; c++)
                    s[r][c] += rq[r] * rk[c];
        }

#pragma unroll
        for (int c = 0; c < 4; c++) {
            const float mv = sm.mk[tx * 4 + c];
#pragma unroll
            for (int r = 0; r < 4; r++) s[r][c] += mv;
        }
        if (kt == qt) {
#pragma unroll
            for (int r = 0; r < 4; r++) {
#pragma unroll
                for (int c = 0; c < 4; c++) {
                    const int jg = kt * 64 + tx * 4 + c;
                    if (jg > ig[r]) s[r][c] = -1e30f;
                }
            }
        }

        float rmax[4], rsum[4];
#pragma unroll
        for (int r = 0; r < 4; r++) {
            float mx = fmaxf(fmaxf(s[r][0], s[r][1]), fmaxf(s[r][2], s[r][3]));
#pragma unroll
            for (int o = 1; o < 16; o <<= 1)
                mx = fmaxf(mx, __shfl_xor_sync(0xffffffffu, mx, o));
            rmax[r] = mx;
        }
#pragma unroll
        for (int r = 0; r < 4; r++) {
            const float mnew = fmaxf(m_s[r], rmax[r]);
            const float corr = __expf(m_s[r] - mnew);
            m_s[r] = mnew;
            float su = 0.f;
#pragma unroll
            for (int c = 0; c < 4; c++) {
                s[r][c] = __expf(s[r][c] - mnew);
                su += s[r][c];
            }
            rsum[r] = su;
            l_s[r] *= corr;
#pragma unroll
            for (int c = 0; c < 4; c++) acc[r][c] *= corr;
        }
#pragma unroll
        for (int r = 0; r < 4; r++) {
            float su = rsum[r];
#pragma unroll
            for (int o = 1; o < 16; o <<= 1)
                su += __shfl_xor_sync(0xffffffffu, su, o);
            l_s[r] += su;
        }

#pragma unroll
        for (int r = 0; r < 4; r++)
#pragma unroll
            for (int c = 0; c < 4; c++)
                sm.Ps[ty * 4 + r][tx * 4 + c] = s[r][c];
        __syncthreads();

#pragma unroll 4
        for (int j = 0; j < 64; j++) {
            float pr[4];
#pragma unroll
            for (int r = 0; r < 4; r++) pr[r] = sm.Ps[ty * 4 + r][j];
            float4 vv = *(float4*)&sm.Vs[j][tx * 4];
            float rv[4] = {vv.x, vv.y, vv.z, vv.w};
#pragma unroll
            for (int r = 0; r < 4; r++)
#pragma unroll
                for (int c = 0; c < 4; c++)
                    acc[r][c] += pr[r] * rv[c];
        }
        __syncthreads();
    }

#pragma unroll
    for (int r = 0; r < 4; r++) {
        const float inv = 1.f / l_s[r];
        const int i = ig[r];
        float4 o = make_float4(acc[r][0] * inv, acc[r][1] * inv,
                               acc[r][2] * inv, acc[r][3] * inv);
        *(float4*)&outp[((size_t)b * N_ + i) * HD_ + h * DH_ + tx * 4] = o;
    }
}

// ---------------------------------------------------------------------------
extern "C" void kernel_launch(void* const* d_in, const int* in_sizes, int n_in,
                              void* d_out, int out_size)
{
    const float* x     = (const float*)d_in[0];
    const int*   mask  = (const int*)d_in[1];     // bool -> int32 in harness
    const float* w_qkv = (const float*)d_in[2];
    const float* w_out = (const float*)d_in[3];
    const float* b_out = (const float*)d_in[4];
    float* out = (float*)d_out;

    float *qkv_buf = nullptr, *attn_buf = nullptr;
    cudaGetSymbolAddress((void**)&qkv_buf, g_qkv);
    cudaGetSymbolAddress((void**)&attn_buf, g_attn);

    cudaFuncSetAttribute(flash_attn_kernel,
                         cudaFuncAttributeMaxDynamicSharedMemorySize,
                         (int)sizeof(AttnSmem));

    const int M = B_ * N_;   // 8192

    // 1) QKV projection: [8192,1024] @ [1024,3072]  (tf32 tensor cores)
    gemm_tf32_kernel<false><<<dim3(QKV_COLS / 128, M / 128), 256>>>(
        x, w_qkv, nullptr, qkv_buf, M, QKV_COLS, DIM_);

    // 2) causal flash attention (fp32)
    flash_attn_kernel<<<dim3(N_ / 64, H_, B_), 256, sizeof(AttnSmem)>>>(
        qkv_buf, mask, attn_buf);

    // 3) output projection + bias: [8192,1024] @ [1024,1024]  (tf32)
    gemm_tf32_kernel<true><<<dim3(DIM_ / 128, M / 128), 256>>>(
        attn_buf, w_out, b_out, out, M, DIM_, DIM_);
}

// round 4
// speedup vs baseline: 1.7676x; 1.7520x over previous
#include <cuda_runtime.h>
#include <cuda_fp16.h>
#include <cstdint>
#include <cstddef>

// Problem shapes (fixed per reference)
#define B_ 4
#define N_ 2048
#define DIM_ 1024
#define H_ 16
#define DH_ 64
#define QKV_COLS (3 * H_ * DH_)   // 3072
#define HD_ (H_ * DH_)            // 1024

// Scratch: __device__ globals (allocation-free rule)
__device__ float  g_qkv[(size_t)B_ * N_ * QKV_COLS];    // [B,N,3072] f32
__device__ float  g_attn[(size_t)B_ * N_ * HD_];        // [B,N,1024] f32
__device__ __half g_xh[(size_t)B_ * N_ * DIM_];         // x in f16
__device__ __half g_wqkvh[(size_t)DIM_ * QKV_COLS];     // w_qkv f16
__device__ __half g_wouth[(size_t)HD_ * DIM_];          // w_out f16
__device__ __half g_attnh[(size_t)B_ * N_ * HD_];       // attn out f16

// ---------------------------------------------------------------------------
// f32 -> f16 conversion (vectorized), n % 4 == 0
// ---------------------------------------------------------------------------
__global__ void f32_to_f16_kernel(const float* __restrict__ in,
                                  __half* __restrict__ out, int n)
{
    int i = (blockIdx.x * blockDim.x + threadIdx.x) * 4;
    if (i < n) {
        float4 v = *(const float4*)(in + i);
        __half2 h0 = __floats2half2_rn(v.x, v.y);
        __half2 h1 = __floats2half2_rn(v.z, v.w);
        uint2 pk;
        pk.x = *(uint32_t*)&h0;
        pk.y = *(uint32_t*)&h1;
        *(uint2*)(out + i) = pk;
    }
}

// ---------------------------------------------------------------------------
// PTX helpers
// ---------------------------------------------------------------------------
__device__ __forceinline__ uint32_t smem_u32(const void* p) {
    return (uint32_t)__cvta_generic_to_shared(p);
}

__device__ __forceinline__ void cp_async16(uint32_t dst, const void* src) {
    asm volatile("cp.async.cg.shared.global [%0], [%1], 16;\n"
                 :: "r"(dst), "l"(src));
}
__device__ __forceinline__ void cp_commit() {
    asm volatile("cp.async.commit_group;\n");
}
template<int NN>
__device__ __forceinline__ void cp_wait() {
    asm volatile("cp.async.wait_group %0;\n" :: "n"(NN));
}

__device__ __forceinline__ void ldsm_x4(uint32_t* r, uint32_t addr) {
    asm volatile("ldmatrix.sync.aligned.m8n8.x4.shared.b16 {%0,%1,%2,%3}, [%4];\n"
                 : "=r"(r[0]), "=r"(r[1]), "=r"(r[2]), "=r"(r[3]) : "r"(addr));
}
__device__ __forceinline__ void ldsm_x4_t(uint32_t* r, uint32_t addr) {
    asm volatile("ldmatrix.sync.aligned.m8n8.x4.trans.shared.b16 {%0,%1,%2,%3}, [%4];\n"
                 : "=r"(r[0]), "=r"(r[1]), "=r"(r[2]), "=r"(r[3]) : "r"(addr));
}

__device__ __forceinline__ void mma_f16_16816(
    float& d0, float& d1, float& d2, float& d3,
    uint32_t a0, uint32_t a1, uint32_t a2, uint32_t a3,
    uint32_t b0, uint32_t b1)
{
    asm volatile(
        "mma.sync.aligned.m16n8k16.row.col.f32.f16.f16.f32 "
        "{%0,%1,%2,%3}, {%4,%5,%6,%7}, {%8,%9}, {%0,%1,%2,%3};\n"
        : "+f"(d0), "+f"(d1), "+f"(d2), "+f"(d3)
        : "r"(a0), "r"(a1), "r"(a2), "r"(a3), "r"(b0), "r"(b1));
}

// ---------------------------------------------------------------------------
// fp16 HGEMM: C[M,Nc](f32) = A[M,K](f16) @ B[K,Nc](f16) (+bias f32)
// BM=128, BN=128, BK=32. 8 warps (2m x 4n), warp tile 64x32.
// 3-stage cp.async pipeline. Padded rows for conflict-free LDSM:
//   A stage: [128][40] halves (80B row stride)
//   B stage: [32][136] halves (272B row stride)
// ---------------------------------------------------------------------------
#define A_STRIDE 40           // halves
#define B_STRIDE 136          // halves
#define A_STAGE_BYTES (128 * A_STRIDE * 2)   // 10240
#define B_STAGE_BYTES (32 * B_STRIDE * 2)    // 8704
#define STAGE_BYTES (A_STAGE_BYTES + B_STAGE_BYTES)  // 18944
#define NSTAGE 3

template<bool HAS_BIAS>
__global__ __launch_bounds__(256, 2) void hgemm_kernel(
    const __half* __restrict__ A, const __half* __restrict__ Bm,
    const float* __restrict__ bias, float* __restrict__ C,
    int M, int Nc, int K)
{
    extern __shared__ char smem[];

    const int tid  = threadIdx.x;
    const int lane = tid & 31;
    const int wid  = tid >> 5;
    const int warp_m = wid >> 2;    // 0..1
    const int warp_n = wid & 3;     // 0..3
    const int m0 = blockIdx.y * 128;
    const int n0 = blockIdx.x * 128;
    const int NT = K >> 5;          // k-tiles of 32

    float acc[4][4][4];
#pragma unroll
    for (int mt = 0; mt < 4; mt++)
#pragma unroll
        for (int nt = 0; nt < 4; nt++)
#pragma unroll
            for (int r = 0; r < 4; r++) acc[mt][nt][r] = 0.f;

    // cp.async chunk coords (16B = 8 halves per chunk)
    // A tile: 128 rows x 4 chunks = 512 chunks; 2 per thread
    const int aq0 = tid * 2;
    // B tile: 32 rows x 16 chunks = 512 chunks; 2 per thread
    const int bq0 = tid * 2;

    auto stage_ptr = [&](int s) -> char* { return smem + s * STAGE_BYTES; };

    auto load_tile = [&](int kt, int s) {
        char* Ab = stage_ptr(s);
        char* Bb = Ab + A_STAGE_BYTES;
#pragma unroll
        for (int q = 0; q < 2; q++) {
            const int aq = aq0 + q;
            const int ar = aq >> 2, ac = aq & 3;          // row, chunk
            cp_async16(smem_u32(Ab + ar * (A_STRIDE * 2) + ac * 16),
                       A + (size_t)(m0 + ar) * K + kt * 32 + ac * 8);
            const int bq = bq0 + q;
            const int br = bq >> 4, bc = bq & 15;
            cp_async16(smem_u32(Bb + br * (B_STRIDE * 2) + bc * 16),
                       Bm + (size_t)(kt * 32 + br) * Nc + n0 + bc * 8);
        }
        cp_commit();
    };

    // prologue: fill 2 stages
    load_tile(0, 0);
    load_tile(1, 1);
    cp_wait<1>();
    __syncthreads();

    // LDSM lane address components
    const int lrow = (lane & 7) + 8 * ((lane >> 3) & 1);  // row within 16-block
    const int lcol = 8 * (lane >> 4);                     // halves offset (0 or 8)

    for (int kt = 0; kt < NT; kt++) {
        const int s = kt % NSTAGE;
        const __half* Ah = (const __half*)stage_ptr(s);
        const __half* Bh = (const __half*)(stage_ptr(s) + A_STAGE_BYTES);

#pragma unroll
        for (int ks = 0; ks < 2; ks++) {
            uint32_t af[4][4];
#pragma unroll
            for (int mt = 0; mt < 4; mt++) {
                const int row = warp_m * 64 + mt * 16 + lrow;
                ldsm_x4(af[mt], smem_u32(Ah + row * A_STRIDE + ks * 16 + lcol));
            }
            uint32_t bf[4][2];
#pragma unroll
            for (int np = 0; np < 2; np++) {
                uint32_t t[4];
                const int krow = ks * 16 + lrow;
                ldsm_x4_t(t, smem_u32(Bh + krow * B_STRIDE
                                         + warp_n * 32 + np * 16 + lcol));
                bf[np * 2 + 0][0] = t[0]; bf[np * 2 + 0][1] = t[1];
                bf[np * 2 + 1][0] = t[2]; bf[np * 2 + 1][1] = t[3];
            }
#pragma unroll
            for (int mt = 0; mt < 4; mt++)
#pragma unroll
                for (int nt = 0; nt < 4; nt++)
                    mma_f16_16816(acc[mt][nt][0], acc[mt][nt][1],
                                  acc[mt][nt][2], acc[mt][nt][3],
                                  af[mt][0], af[mt][1], af[mt][2], af[mt][3],
                                  bf[nt][0], bf[nt][1]);
        }

        // prefetch tile kt+2 into stage (kt+2)%3 (computed at iter kt-1; all
        // warps are past it thanks to the syncthreads at the end of kt-1)
        if (kt + 2 < NT) load_tile(kt + 2, (kt + 2) % NSTAGE);
        else cp_commit();   // keep group count uniform
        cp_wait<1>();
        __syncthreads();
    }

    // epilogue: c frag -> C. row = lane/4 (+8), col = 2*(lane%4) (+1)
#pragma unroll
    for (int mt = 0; mt < 4; mt++) {
#pragma unroll
        for (int nt = 0; nt < 4; nt++) {
            const int r0 = m0 + warp_m * 64 + mt * 16 + (lane >> 2);
            const int c0 = n0 + warp_n * 32 + nt * 8 + (lane & 3) * 2;
            float2 lo = make_float2(acc[mt][nt][0], acc[mt][nt][1]);
            float2 hi = make_float2(acc[mt][nt][2], acc[mt][nt][3]);
            if (HAS_BIAS) {
                const float b0v = bias[c0], b1v = bias[c0 + 1];
                lo.x += b0v; lo.y += b1v;
                hi.x += b0v; hi.y += b1v;
            }
            *(float2*)(C + (size_t)r0 * Nc + c0)       = lo;
            *(float2*)(C + (size_t)(r0 + 8) * Nc + c0) = hi;
        }
    }
}

// ---------------------------------------------------------------------------
// Flash attention (causal + key-padding mask), fp32 (unchanged).
// ---------------------------------------------------------------------------
struct AttnSmem {
    float Qt[64][64];
    float Kt[64][64];
    float Vs[64][68];
    float Ps[64][68];
    float mk[64];
};

__global__ __launch_bounds__(256, 3) void flash_attn_kernel(
    const float* __restrict__ qkv, const int* __restrict__ mask,
    float* __restrict__ outp)
{
    extern __shared__ char smem_raw[];
    AttnSmem& sm = *reinterpret_cast<AttnSmem*>(smem_raw);

    const int qt = blockIdx.x;
    const int h  = blockIdx.y;
    const int b  = blockIdx.z;
    const int tid = threadIdx.x;
    const int tx = tid & 15;
    const int ty = tid >> 4;

    const float scale = 0.125f;

    const float* qbase = qkv + (size_t)b * N_ * QKV_COLS + h * DH_;
    const float* kbase = qbase + HD_;
    const float* vbase = qbase + 2 * HD_;

    {
        const int r = tid >> 2;
        const int d0 = (tid & 3) * 16;
        const int ig = qt * 64 + r;
        const float* qr = qbase + (size_t)ig * QKV_COLS + d0;
#pragma unroll
        for (int dd = 0; dd < 16; dd++)
            sm.Qt[d0 + dd][r] = qr[dd] * scale;
    }

    float m_s[4], l_s[4], acc[4][4];
#pragma unroll
    for (int r = 0; r < 4; r++) {
        m_s[r] = -1e30f; l_s[r] = 0.f;
#pragma unroll
        for (int c = 0; c < 4; c++) acc[r][c] = 0.f;
    }
    int ig[4];
#pragma unroll
    for (int r = 0; r < 4; r++) ig[r] = qt * 64 + ty * 4 + r;

    for (int kt = 0; kt <= qt; kt++) {
        {
            const int j = tid >> 2;
            const int d0 = (tid & 3) * 16;
            const int jg = kt * 64 + j;
            const float* kr = kbase + (size_t)jg * QKV_COLS + d0;
            const float* vr = vbase + (size_t)jg * QKV_COLS + d0;
#pragma unroll
            for (int dd = 0; dd < 16; dd++) {
                sm.Kt[d0 + dd][j] = kr[dd];
                sm.Vs[j][d0 + dd] = vr[dd];
            }
            if (tid < 64)
                sm.mk[tid] = (mask[(size_t)b * N_ + kt * 64 + tid] != 0) ? 0.f : -1e30f;
        }
        __syncthreads();

        float s[4][4];
#pragma unroll
        for (int r = 0; r < 4; r++)
#pragma unroll
            for (int c = 0; c < 4; c++) s[r][c] = 0.f;

#pragma unroll 8
        for (int d = 0; d < 64; d++) {
            float4 qv = *(float4*)&sm.Qt[d][ty * 4];
            float4 kv = *(float4*)&sm.Kt[d][tx * 4];
            float rq[4] = {qv.x, qv.y, qv.z, qv.w};
            float rk[4] = {kv.x, kv.y, kv.z, kv.w};
#pragma unroll
            for (int r = 0; r < 4; r++)
#pragma unroll
                for (int c = 0; c < 4; c++)
                    s[r][c] += rq[r] * rk[c];
        }

#pragma unroll
        for (int c = 0; c < 4; c++) {
            const float mv = sm.mk[tx * 4 + c];
#pragma unroll
            for (int r = 0; r < 4; r++) s[r][c] += mv;
        }
        if (kt == qt) {
#pragma unroll
            for (int r = 0; r < 4; r++) {
#pragma unroll
                for (int c = 0; c < 4; c++) {
                    const int jg = kt * 64 + tx * 4 + c;
                    if (jg > ig[r]) s[r][c] = -1e30f;
                }
            }
        }

        float rmax[4], rsum[4];
#pragma unroll
        for (int r = 0; r < 4; r++) {
            float mx = fmaxf(fmaxf(s[r][0], s[r][1]), fmaxf(s[r][2], s[r][3]));
#pragma unroll
            for (int o = 1; o < 16; o <<= 1)
                mx = fmaxf(mx, __shfl_xor_sync(0xffffffffu, mx, o));
            rmax[r] = mx;
        }
#pragma unroll
        for (int r = 0; r < 4; r++) {
            const float mnew = fmaxf(m_s[r], rmax[r]);
            const float corr = __expf(m_s[r] - mnew);
            m_s[r] = mnew;
            float su = 0.f;
#pragma unroll
            for (int c = 0; c < 4; c++) {
                s[r][c] = __expf(s[r][c] - mnew);
                su += s[r][c];
            }
            rsum[r] = su;
            l_s[r] *= corr;
#pragma unroll
            for (int c = 0; c < 4; c++) acc[r][c] *= corr;
        }
#pragma unroll
        for (int r = 0; r < 4; r++) {
            float su = rsum[r];
#pragma unroll
            for (int o = 1; o < 16; o <<= 1)
                su += __shfl_xor_sync(0xffffffffu, su, o);
            l_s[r] += su;
        }

#pragma unroll
        for (int r = 0; r < 4; r++)
#pragma unroll
            for (int c = 0; c < 4; c++)
                sm.Ps[ty * 4 + r][tx * 4 + c] = s[r][c];
        __syncthreads();

#pragma unroll 4
        for (int j = 0; j < 64; j++) {
            float pr[4];
#pragma unroll
            for (int r = 0; r < 4; r++) pr[r] = sm.Ps[ty * 4 + r][j];
            float4 vv = *(float4*)&sm.Vs[j][tx * 4];
            float rv[4] = {vv.x, vv.y, vv.z, vv.w};
#pragma unroll
            for (int r = 0; r < 4; r++)
#pragma unroll
                for (int c = 0; c < 4; c++)
                    acc[r][c] += pr[r] * rv[c];
        }
        __syncthreads();
    }

#pragma unroll
    for (int r = 0; r < 4; r++) {
        const float inv = 1.f / l_s[r];
        const int i = ig[r];
        float4 o = make_float4(acc[r][0] * inv, acc[r][1] * inv,
                               acc[r][2] * inv, acc[r][3] * inv);
        *(float4*)&outp[((size_t)b * N_ + i) * HD_ + h * DH_ + tx * 4] = o;
    }
}

// ---------------------------------------------------------------------------
extern "C" void kernel_launch(void* const* d_in, const int* in_sizes, int n_in,
                              void* d_out, int out_size)
{
    const float* x     = (const float*)d_in[0];
    const int*   mask  = (const int*)d_in[1];     // bool -> int32 in harness
    const float* w_qkv = (const float*)d_in[2];
    const float* w_out = (const float*)d_in[3];
    const float* b_out = (const float*)d_in[4];
    float* out = (float*)d_out;

    float  *qkv_buf = nullptr, *attn_buf = nullptr;
    __half *xh = nullptr, *wqkvh = nullptr, *wouth = nullptr, *attnh = nullptr;
    cudaGetSymbolAddress((void**)&qkv_buf, g_qkv);
    cudaGetSymbolAddress((void**)&attn_buf, g_attn);
    cudaGetSymbolAddress((void**)&xh, g_xh);
    cudaGetSymbolAddress((void**)&wqkvh, g_wqkvh);
    cudaGetSymbolAddress((void**)&wouth, g_wouth);
    cudaGetSymbolAddress((void**)&attnh, g_attnh);

    cudaFuncSetAttribute(flash_attn_kernel,
                         cudaFuncAttributeMaxDynamicSharedMemorySize,
                         (int)sizeof(AttnSmem));
    cudaFuncSetAttribute(hgemm_kernel<false>,
                         cudaFuncAttributeMaxDynamicSharedMemorySize,
                         NSTAGE * STAGE_BYTES);
    cudaFuncSetAttribute(hgemm_kernel<true>,
                         cudaFuncAttributeMaxDynamicSharedMemorySize,
                         NSTAGE * STAGE_BYTES);

    const int M = B_ * N_;   // 8192

    // 0) convert inputs to f16
    {
        const int nx = B_ * N_ * DIM_;
        f32_to_f16_kernel<<<(nx / 4 + 255) / 256, 256>>>(x, xh, nx);
        const int nw = DIM_ * QKV_COLS;
        f32_to_f16_kernel<<<(nw / 4 + 255) / 256, 256>>>(w_qkv, wqkvh, nw);
        const int no = HD_ * DIM_;
        f32_to_f16_kernel<<<(no / 4 + 255) / 256, 256>>>(w_out, wouth, no);
    }

    // 1) QKV projection: [8192,1024] @ [1024,3072] (f16 MMA, f32 out)
    hgemm_kernel<false><<<dim3(QKV_COLS / 128, M / 128), 256,
                          NSTAGE * STAGE_BYTES>>>(
        xh, wqkvh, nullptr, qkv_buf, M, QKV_COLS, DIM_);

    // 2) causal flash attention (fp32)
    flash_attn_kernel<<<dim3(N_ / 64, H_, B_), 256, sizeof(AttnSmem)>>>(
        qkv_buf, mask, attn_buf);

    // 2b) convert attention output to f16
    {
        const int na = B_ * N_ * HD_;
        f32_to_f16_kernel<<<(na / 4 + 255) / 256, 256>>>(attn_buf, attnh, na);
    }

    // 3) output projection + bias: [8192,1024] @ [1024,1024]
    hgemm_kernel<true><<<dim3(DIM_ / 128, M / 128), 256,
                         NSTAGE * STAGE_BYTES>>>(
        attnh, wouth, b_out, out, M, DIM_, DIM_);
}

// round 5
// speedup vs baseline: 7.4386x; 4.2083x over previous
#include <cuda_runtime.h>
#include <cuda_fp16.h>
#include <cstdint>
#include <cstddef>

// Problem shapes (fixed per reference)
#define B_ 4
#define N_ 2048
#define DIM_ 1024
#define H_ 16
#define DH_ 64
#define QKV_COLS (3 * H_ * DH_)   // 3072
#define HD_ (H_ * DH_)            // 1024

// Scratch: __device__ globals (allocation-free rule)
__device__ __half g_qkvh[(size_t)B_ * N_ * QKV_COLS];   // qkv f16
__device__ __half g_xh[(size_t)B_ * N_ * DIM_];         // x f16
__device__ __half g_wqkvh[(size_t)DIM_ * QKV_COLS];     // w_qkv f16
__device__ __half g_wouth[(size_t)HD_ * DIM_];          // w_out f16
__device__ __half g_attnh[(size_t)B_ * N_ * HD_];       // attn out f16

// ---------------------------------------------------------------------------
// f32 -> f16 conversion (vectorized), n % 4 == 0
// ---------------------------------------------------------------------------
__global__ void f32_to_f16_kernel(const float* __restrict__ in,
                                  __half* __restrict__ out, int n)
{
    int i = (blockIdx.x * blockDim.x + threadIdx.x) * 4;
    if (i < n) {
        float4 v = *(const float4*)(in + i);
        __half2 h0 = __floats2half2_rn(v.x, v.y);
        __half2 h1 = __floats2half2_rn(v.z, v.w);
        uint2 pk;
        pk.x = *(uint32_t*)&h0;
        pk.y = *(uint32_t*)&h1;
        *(uint2*)(out + i) = pk;
    }
}

// ---------------------------------------------------------------------------
// PTX helpers
// ---------------------------------------------------------------------------
__device__ __forceinline__ uint32_t smem_u32(const void* p) {
    return (uint32_t)__cvta_generic_to_shared(p);
}
__device__ __forceinline__ void cp_async16(uint32_t dst, const void* src) {
    asm volatile("cp.async.cg.shared.global [%0], [%1], 16;\n"
                 :: "r"(dst), "l"(src));
}
__device__ __forceinline__ void cp_commit() {
    asm volatile("cp.async.commit_group;\n");
}
template<int NN>
__device__ __forceinline__ void cp_wait() {
    asm volatile("cp.async.wait_group %0;\n" :: "n"(NN));
}
__device__ __forceinline__ void ldsm_x4(uint32_t* r, uint32_t addr) {
    asm volatile("ldmatrix.sync.aligned.m8n8.x4.shared.b16 {%0,%1,%2,%3}, [%4];\n"
                 : "=r"(r[0]), "=r"(r[1]), "=r"(r[2]), "=r"(r[3]) : "r"(addr));
}
__device__ __forceinline__ void ldsm_x4_t(uint32_t* r, uint32_t addr) {
    asm volatile("ldmatrix.sync.aligned.m8n8.x4.trans.shared.b16 {%0,%1,%2,%3}, [%4];\n"
                 : "=r"(r[0]), "=r"(r[1]), "=r"(r[2]), "=r"(r[3]) : "r"(addr));
}
__device__ __forceinline__ void mma_f16_16816(
    float& d0, float& d1, float& d2, float& d3,
    uint32_t a0, uint32_t a1, uint32_t a2, uint32_t a3,
    uint32_t b0, uint32_t b1)
{
    asm volatile(
        "mma.sync.aligned.m16n8k16.row.col.f32.f16.f16.f32 "
        "{%0,%1,%2,%3}, {%4,%5,%6,%7}, {%8,%9}, {%0,%1,%2,%3};\n"
        : "+f"(d0), "+f"(d1), "+f"(d2), "+f"(d3)
        : "r"(a0), "r"(a1), "r"(a2), "r"(a3), "r"(b0), "r"(b1));
}
__device__ __forceinline__ uint32_t pack_h2(float a, float b) {
    __half2 h = __floats2half2_rn(a, b);
    return *(uint32_t*)&h;
}

// ---------------------------------------------------------------------------
// fp16 HGEMM: C[M,Nc] = A[M,K](f16) @ B[K,Nc](f16) (+bias f32), OutT f32/f16
// BM=128, BN=128, BK=32, 8 warps (2m x 4n), 3-stage cp.async pipeline.
// ---------------------------------------------------------------------------
#define A_STRIDE 40           // halves
#define B_STRIDE 136          // halves
#define A_STAGE_BYTES (128 * A_STRIDE * 2)   // 10240
#define B_STAGE_BYTES (32 * B_STRIDE * 2)    // 8704
#define STAGE_BYTES (A_STAGE_BYTES + B_STAGE_BYTES)  // 18944
#define NSTAGE 3

template<bool HAS_BIAS, typename OutT>
__global__ __launch_bounds__(256, 2) void hgemm_kernel(
    const __half* __restrict__ A, const __half* __restrict__ Bm,
    const float* __restrict__ bias, OutT* __restrict__ C,
    int M, int Nc, int K)
{
    extern __shared__ char smem[];

    const int tid  = threadIdx.x;
    const int lane = tid & 31;
    const int wid  = tid >> 5;
    const int warp_m = wid >> 2;
    const int warp_n = wid & 3;
    const int m0 = blockIdx.y * 128;
    const int n0 = blockIdx.x * 128;
    const int NT = K >> 5;

    float acc[4][4][4];
#pragma unroll
    for (int mt = 0; mt < 4; mt++)
#pragma unroll
        for (int nt = 0; nt < 4; nt++)
#pragma unroll
            for (int r = 0; r < 4; r++) acc[mt][nt][r] = 0.f;

    const int aq0 = tid * 2;
    const int bq0 = tid * 2;

    auto stage_ptr = [&](int s) -> char* { return smem + s * STAGE_BYTES; };

    auto load_tile = [&](int kt, int s) {
        char* Ab = stage_ptr(s);
        char* Bb = Ab + A_STAGE_BYTES;
#pragma unroll
        for (int q = 0; q < 2; q++) {
            const int aq = aq0 + q;
            const int ar = aq >> 2, ac = aq & 3;
            cp_async16(smem_u32(Ab + ar * (A_STRIDE * 2) + ac * 16),
                       A + (size_t)(m0 + ar) * K + kt * 32 + ac * 8);
            const int bq = bq0 + q;
            const int br = bq >> 4, bc = bq & 15;
            cp_async16(smem_u32(Bb + br * (B_STRIDE * 2) + bc * 16),
                       Bm + (size_t)(kt * 32 + br) * Nc + n0 + bc * 8);
        }
        cp_commit();
    };

    load_tile(0, 0);
    load_tile(1, 1);
    cp_wait<1>();
    __syncthreads();

    const int lrow = (lane & 7) + 8 * ((lane >> 3) & 1);
    const int lcol = 8 * (lane >> 4);

    for (int kt = 0; kt < NT; kt++) {
        const int s = kt % NSTAGE;
        const __half* Ah = (const __half*)stage_ptr(s);
        const __half* Bh = (const __half*)(stage_ptr(s) + A_STAGE_BYTES);

#pragma unroll
        for (int ks = 0; ks < 2; ks++) {
            uint32_t af[4][4];
#pragma unroll
            for (int mt = 0; mt < 4; mt++) {
                const int row = warp_m * 64 + mt * 16 + lrow;
                ldsm_x4(af[mt], smem_u32(Ah + row * A_STRIDE + ks * 16 + lcol));
            }
            uint32_t bf[4][2];
#pragma unroll
            for (int np = 0; np < 2; np++) {
                uint32_t t[4];
                const int krow = ks * 16 + lrow;
                ldsm_x4_t(t, smem_u32(Bh + krow * B_STRIDE
                                         + warp_n * 32 + np * 16 + lcol));
                bf[np * 2 + 0][0] = t[0]; bf[np * 2 + 0][1] = t[1];
                bf[np * 2 + 1][0] = t[2]; bf[np * 2 + 1][1] = t[3];
            }
#pragma unroll
            for (int mt = 0; mt < 4; mt++)
#pragma unroll
                for (int nt = 0; nt < 4; nt++)
                    mma_f16_16816(acc[mt][nt][0], acc[mt][nt][1],
                                  acc[mt][nt][2], acc[mt][nt][3],
                                  af[mt][0], af[mt][1], af[mt][2], af[mt][3],
                                  bf[nt][0], bf[nt][1]);
        }

        if (kt + 2 < NT) load_tile(kt + 2, (kt + 2) % NSTAGE);
        else cp_commit();
        cp_wait<1>();
        __syncthreads();
    }

#pragma unroll
    for (int mt = 0; mt < 4; mt++) {
#pragma unroll
        for (int nt = 0; nt < 4; nt++) {
            const int r0 = m0 + warp_m * 64 + mt * 16 + (lane >> 2);
            const int c0 = n0 + warp_n * 32 + nt * 8 + (lane & 3) * 2;
            float2 lo = make_float2(acc[mt][nt][0], acc[mt][nt][1]);
            float2 hi = make_float2(acc[mt][nt][2], acc[mt][nt][3]);
            if (HAS_BIAS) {
                const float b0v = bias[c0], b1v = bias[c0 + 1];
                lo.x += b0v; lo.y += b1v;
                hi.x += b0v; hi.y += b1v;
            }
            if (sizeof(OutT) == 4) {
                *(float2*)((float*)C + (size_t)r0 * Nc + c0)       = lo;
                *(float2*)((float*)C + (size_t)(r0 + 8) * Nc + c0) = hi;
            } else {
                __half2 hlo = __floats2half2_rn(lo.x, lo.y);
                __half2 hhi = __floats2half2_rn(hi.x, hi.y);
                *(__half2*)((__half*)C + (size_t)r0 * Nc + c0)       = hlo;
                *(__half2*)((__half*)C + (size_t)(r0 + 8) * Nc + c0) = hhi;
            }
        }
    }
}

// ---------------------------------------------------------------------------
// fp16 tensor-core flash attention (causal + key padding).
// Block = (q-tile 128, h, b). 8 warps x 16 q-rows. K/V tiles of 64,
// double-buffered cp.async. P kept in registers (C-frag == A-frag layout).
// ---------------------------------------------------------------------------
struct FlashSmem {
    __half Qs[128][72];     // 18432 B
    __half Ks[2][64][72];   // 18432 B
    __half Vs[2][64][72];   // 18432 B
    float  mk[2][64];       // 512 B
};

__global__ __launch_bounds__(256) void flash_f16_kernel(
    const __half* __restrict__ qkv, const int* __restrict__ mask,
    __half* __restrict__ outp)
{
    extern __shared__ char smem_raw[];
    FlashSmem& sm = *reinterpret_cast<FlashSmem*>(smem_raw);

    const int qt = blockIdx.x;
    const int h  = blockIdx.y;
    const int b  = blockIdx.z;
    const int tid  = threadIdx.x;
    const int lane = tid & 31;
    const int w    = tid >> 5;

    const int lrow = (lane & 7) + 8 * ((lane >> 3) & 1);
    const int lcol = 8 * (lane >> 4);
    const int lq   = lane >> 2;        // 0..7
    const int lc2  = (lane & 3) * 2;   // 0,2,4,6

    const __half* qg = qkv + ((size_t)(b * N_ + qt * 128)) * QKV_COLS + h * DH_;

    auto load_kv = [&](int jt, int st) {
        const __half* kg = qkv + ((size_t)(b * N_ + jt * 64)) * QKV_COLS + HD_ + h * DH_;
        const __half* vg = kg + HD_;
#pragma unroll
        for (int q = 0; q < 2; q++) {
            const int c = tid * 2 + q;
            const int r = c >> 3, off = (c & 7) * 8;
            cp_async16(smem_u32(&sm.Ks[st][r][off]), kg + (size_t)r * QKV_COLS + off);
            cp_async16(smem_u32(&sm.Vs[st][r][off]), vg + (size_t)r * QKV_COLS + off);
        }
        if (tid < 64)
            sm.mk[st][tid] = (mask[(size_t)b * N_ + jt * 64 + tid] != 0) ? 0.f : -1e30f;
    };

    // prologue: Q + tile 0
#pragma unroll
    for (int q = 0; q < 4; q++) {
        const int c = tid * 4 + q;
        const int r = c >> 3, off = (c & 7) * 8;
        cp_async16(smem_u32(&sm.Qs[r][off]), qg + (size_t)r * QKV_COLS + off);
    }
    load_kv(0, 0);
    cp_commit();
    cp_wait<0>();
    __syncthreads();

    // Q fragments (scaled by dh^-0.5 = 0.125)
    uint32_t qf[4][4];
    {
        const __half2 sc = __float2half2_rn(0.125f);
#pragma unroll
        for (int dc = 0; dc < 4; dc++) {
            ldsm_x4(qf[dc], smem_u32(&sm.Qs[w * 16 + lrow][dc * 16 + lcol]));
#pragma unroll
            for (int i = 0; i < 4; i++) {
                __half2 v = *(__half2*)&qf[dc][i];
                v = __hmul2(v, sc);
                qf[dc][i] = *(uint32_t*)&v;
            }
        }
    }

    float o[8][4];
#pragma unroll
    for (int dt = 0; dt < 8; dt++)
#pragma unroll
        for (int r = 0; r < 4; r++) o[dt][r] = 0.f;
    float m0 = -1e30f, m1 = -1e30f, l0 = 0.f, l1 = 0.f;

    const int ig0 = qt * 128 + w * 16 + lq;   // global q row (lower)
    const int njt = 2 * qt + 2;

    for (int jt = 0; jt < njt; jt++) {
        const int st = jt & 1;
        if (jt + 1 < njt) load_kv(jt + 1, (jt + 1) & 1);
        cp_commit();
        cp_wait<1>();
        __syncthreads();

        // ---- S = Q K^T ----
        float s[8][4];
#pragma unroll
        for (int nt = 0; nt < 8; nt++)
#pragma unroll
            for (int r = 0; r < 4; r++) s[nt][r] = 0.f;

#pragma unroll
        for (int dc = 0; dc < 4; dc++) {
#pragma unroll
            for (int grp = 0; grp < 2; grp++) {
                uint32_t t0[4], t1[4];
                const int krow = grp * 32 + (lane >> 3) * 8 + (lane & 7);
                ldsm_x4(t0, smem_u32(&sm.Ks[st][krow][dc * 16 + 0]));
                ldsm_x4(t1, smem_u32(&sm.Ks[st][krow][dc * 16 + 8]));
#pragma unroll
                for (int mI = 0; mI < 4; mI++) {
                    const int nt = grp * 4 + mI;
                    mma_f16_16816(s[nt][0], s[nt][1], s[nt][2], s[nt][3],
                                  qf[dc][0], qf[dc][1], qf[dc][2], qf[dc][3],
                                  t0[mI], t1[mI]);
                }
            }
        }

        // ---- masks ----
#pragma unroll
        for (int nt = 0; nt < 8; nt++) {
            const float pa = sm.mk[st][nt * 8 + lc2];
            const float pb = sm.mk[st][nt * 8 + lc2 + 1];
            s[nt][0] += pa; s[nt][1] += pb;
            s[nt][2] += pa; s[nt][3] += pb;
        }
        if (jt >= 2 * qt) {
#pragma unroll
            for (int nt = 0; nt < 8; nt++) {
                const int jg = jt * 64 + nt * 8 + lc2;
                if (jg > ig0)     s[nt][0] = -1e30f;
                if (jg + 1 > ig0) s[nt][1] = -1e30f;
                if (jg > ig0 + 8)     s[nt][2] = -1e30f;
                if (jg + 1 > ig0 + 8) s[nt][3] = -1e30f;
            }
        }

        // ---- online softmax (rows ig0, ig0+8) ----
        float mx0 = -1e30f, mx1 = -1e30f;
#pragma unroll
        for (int nt = 0; nt < 8; nt++) {
            mx0 = fmaxf(mx0, fmaxf(s[nt][0], s[nt][1]));
            mx1 = fmaxf(mx1, fmaxf(s[nt][2], s[nt][3]));
        }
        mx0 = fmaxf(mx0, __shfl_xor_sync(0xffffffffu, mx0, 1));
        mx0 = fmaxf(mx0, __shfl_xor_sync(0xffffffffu, mx0, 2));
        mx1 = fmaxf(mx1, __shfl_xor_sync(0xffffffffu, mx1, 1));
        mx1 = fmaxf(mx1, __shfl_xor_sync(0xffffffffu, mx1, 2));

        const float mn0 = fmaxf(m0, mx0);
        const float mn1 = fmaxf(m1, mx1);
        const float cr0 = __expf(m0 - mn0);
        const float cr1 = __expf(m1 - mn1);
        m0 = mn0; m1 = mn1;

        float rs0 = 0.f, rs1 = 0.f;
#pragma unroll
        for (int nt = 0; nt < 8; nt++) {
            s[nt][0] = __expf(s[nt][0] - mn0);
            s[nt][1] = __expf(s[nt][1] - mn0);
            s[nt][2] = __expf(s[nt][2] - mn1);
            s[nt][3] = __expf(s[nt][3] - mn1);
            rs0 += s[nt][0] + s[nt][1];
            rs1 += s[nt][2] + s[nt][3];
        }
        rs0 += __shfl_xor_sync(0xffffffffu, rs0, 1);
        rs0 += __shfl_xor_sync(0xffffffffu, rs0, 2);
        rs1 += __shfl_xor_sync(0xffffffffu, rs1, 1);
        rs1 += __shfl_xor_sync(0xffffffffu, rs1, 2);
        l0 = l0 * cr0 + rs0;
        l1 = l1 * cr1 + rs1;

#pragma unroll
        for (int dt = 0; dt < 8; dt++) {
            o[dt][0] *= cr0; o[dt][1] *= cr0;
            o[dt][2] *= cr1; o[dt][3] *= cr1;
        }

        // ---- O += P V ----
#pragma unroll
        for (int jc = 0; jc < 4; jc++) {
            uint32_t pf[4];
            pf[0] = pack_h2(s[2 * jc][0],     s[2 * jc][1]);
            pf[1] = pack_h2(s[2 * jc][2],     s[2 * jc][3]);
            pf[2] = pack_h2(s[2 * jc + 1][0], s[2 * jc + 1][1]);
            pf[3] = pack_h2(s[2 * jc + 1][2], s[2 * jc + 1][3]);
#pragma unroll
            for (int np = 0; np < 4; np++) {
                uint32_t t[4];
                ldsm_x4_t(t, smem_u32(&sm.Vs[st][jc * 16 + lrow][np * 16 + lcol]));
                mma_f16_16816(o[2 * np][0], o[2 * np][1], o[2 * np][2], o[2 * np][3],
                              pf[0], pf[1], pf[2], pf[3], t[0], t[1]);
                mma_f16_16816(o[2 * np + 1][0], o[2 * np + 1][1],
                              o[2 * np + 1][2], o[2 * np + 1][3],
                              pf[0], pf[1], pf[2], pf[3], t[2], t[3]);
            }
        }
        __syncthreads();
    }

    // ---- epilogue ----
    const float inv0 = 1.f / l0;
    const float inv1 = 1.f / l1;
    const int n0g = qt * 128 + w * 16 + lq;
#pragma unroll
    for (int dt = 0; dt < 8; dt++) {
        const int col = h * DH_ + dt * 8 + lc2;
        __half2 v0 = __floats2half2_rn(o[dt][0] * inv0, o[dt][1] * inv0);
        __half2 v1 = __floats2half2_rn(o[dt][2] * inv1, o[dt][3] * inv1);
        *(__half2*)&outp[((size_t)(b * N_ + n0g)) * HD_ + col]     = v0;
        *(__half2*)&outp[((size_t)(b * N_ + n0g + 8)) * HD_ + col] = v1;
    }
}

// ---------------------------------------------------------------------------
extern "C" void kernel_launch(void* const* d_in, const int* in_sizes, int n_in,
                              void* d_out, int out_size)
{
    const float* x     = (const float*)d_in[0];
    const int*   mask  = (const int*)d_in[1];     // bool -> int32 in harness
    const float* w_qkv = (const float*)d_in[2];
    const float* w_out = (const float*)d_in[3];
    const float* b_out = (const float*)d_in[4];
    float* out = (float*)d_out;

    __half *qkvh = nullptr, *xh = nullptr, *wqkvh = nullptr,
           *wouth = nullptr, *attnh = nullptr;
    cudaGetSymbolAddress((void**)&qkvh, g_qkvh);
    cudaGetSymbolAddress((void**)&xh, g_xh);
    cudaGetSymbolAddress((void**)&wqkvh, g_wqkvh);
    cudaGetSymbolAddress((void**)&wouth, g_wouth);
    cudaGetSymbolAddress((void**)&attnh, g_attnh);

    cudaFuncSetAttribute((const void*)hgemm_kernel<false, __half>,
                         cudaFuncAttributeMaxDynamicSharedMemorySize,
                         NSTAGE * STAGE_BYTES);
    cudaFuncSetAttribute((const void*)hgemm_kernel<true, float>,
                         cudaFuncAttributeMaxDynamicSharedMemorySize,
                         NSTAGE * STAGE_BYTES);
    cudaFuncSetAttribute((const void*)flash_f16_kernel,
                         cudaFuncAttributeMaxDynamicSharedMemorySize,
                         (int)sizeof(FlashSmem));

    const int M = B_ * N_;   // 8192

    // 0) convert inputs to f16
    {
        const int nx = B_ * N_ * DIM_;
        f32_to_f16_kernel<<<(nx / 4 + 255) / 256, 256>>>(x, xh, nx);
        const int nw = DIM_ * QKV_COLS;
        f32_to_f16_kernel<<<(nw / 4 + 255) / 256, 256>>>(w_qkv, wqkvh, nw);
        const int no = HD_ * DIM_;
        f32_to_f16_kernel<<<(no / 4 + 255) / 256, 256>>>(w_out, wouth, no);
    }

    // 1) QKV projection -> fp16 qkv
    hgemm_kernel<false, __half><<<dim3(QKV_COLS / 128, M / 128), 256,
                                  NSTAGE * STAGE_BYTES>>>(
        xh, wqkvh, nullptr, qkvh, M, QKV_COLS, DIM_);

    // 2) fp16 tensor-core causal flash attention -> fp16 attn out
    flash_f16_kernel<<<dim3(N_ / 128, H_, B_), 256, sizeof(FlashSmem)>>>(
        qkvh, mask, attnh);

    // 3) output projection + bias -> f32 out
    hgemm_kernel<true, float><<<dim3(DIM_ / 128, M / 128), 256,
                                NSTAGE * STAGE_BYTES>>>(
        attnh, wouth, b_out, out, M, DIM_, DIM_);
}